// round 7
// baseline (speedup 1.0000x reference)
#include <cuda_runtime.h>
#include <cuda_fp16.h>
#include <cstddef>

// LightGCN, CSR-gather, fp16 propagated storage, premultiplied edge weights.
// Per launch:
//   1. stacked degree histogram (int)
//   2. scan1: rs[i] = rsqrt(max(deg,1)) AND exclusive scan of EVEN-PADDED
//      degrees -> CSR offsets (pad slots zeroed by adj memset => contribute 0)
//   3. fill packed adjacency entries (src_id, w = rs[dst]*rs[src]) : 8B each
//   4. t16 = fp16(tables); x1h = gather(t16); x2h = gather(x1h)
//      gather inner loop: int4 load = 2 (id,w) pairs; 1.5 LDG per neighbor
//   5. fused final+score: per batch warp, x3 = gather(x2h) for its 3 nodes,
//      combine 0.25*(x0_fp32+x1+x2+x3), dot products + L2 reg.
//
// All device-global scratch passed via cudaGetSymbolAddress.

#define NU_MAX 100000
#define NI_MAX 50000
#define N_MAX  (NU_MAX + NI_MAX)
#define E_MAX  1600000
#define EMB_D  64
#define SCAN_B 1024
#define ADJ_PAIRS ((2 * E_MAX + N_MAX) / 2 + 8)

__device__ int     g_deg[N_MAX];
__device__ float   g_rs[N_MAX];
__device__ int     g_off[N_MAX + 1];
__device__ int     g_cur[N_MAX];
__device__ int     g_bsum[(N_MAX + SCAN_B) / SCAN_B + 2];
__device__ int4    g_adj4[ADJ_PAIRS];          // 2 entries of (id, w_bits) per int4
__device__ __half2 g_t16[(size_t)N_MAX * (EMB_D / 2)];
__device__ __half2 g_x1h[(size_t)N_MAX * (EMB_D / 2)];
__device__ __half2 g_x2h[(size_t)N_MAX * (EMB_D / 2)];

// ---------------------------------------------------------------------------
// 1. stacked degree histogram
__global__ void deg_kernel(const int* __restrict__ eu, const int* __restrict__ ei,
                           int E, int nu) {
    int e = blockIdx.x * blockDim.x + threadIdx.x;
    if (e < E) {
        atomicAdd(&g_deg[eu[e]], 1);
        atomicAdd(&g_deg[nu + ei[e]], 1);
    }
}

// 2a. per-block exclusive scan over n = N+1 entries of even-padded degrees;
//     also writes rs[i] (fused).
__global__ void scan1_kernel(int n, int N) {
    __shared__ int sh[SCAN_B];
    int tid = threadIdx.x;
    int i = blockIdx.x * SCAN_B + tid;
    int d = (i < N) ? g_deg[i] : 0;
    if (i < N) g_rs[i] = rsqrtf(fmaxf((float)d, 1.0f));
    int v = (d + 1) & ~1;                      // pad degree to even
    sh[tid] = v;
    __syncthreads();
    #pragma unroll
    for (int o = 1; o < SCAN_B; o <<= 1) {
        int t = (tid >= o) ? sh[tid - o] : 0;
        __syncthreads();
        sh[tid] += t;
        __syncthreads();
    }
    if (i < n) g_off[i] = sh[tid] - v;
    if (tid == SCAN_B - 1) g_bsum[blockIdx.x] = sh[tid];
}

__global__ void scan2_kernel(int nb) {
    __shared__ int sh[SCAN_B];
    int tid = threadIdx.x;
    int v = (tid < nb) ? g_bsum[tid] : 0;
    sh[tid] = v;
    __syncthreads();
    #pragma unroll
    for (int o = 1; o < SCAN_B; o <<= 1) {
        int t = (tid >= o) ? sh[tid - o] : 0;
        __syncthreads();
        sh[tid] += t;
        __syncthreads();
    }
    if (tid < nb) g_bsum[tid] = sh[tid] - v;
}

__global__ void scan3_kernel(int n) {
    int i = blockIdx.x * SCAN_B + threadIdx.x;
    if (i < n) g_off[i] += g_bsum[blockIdx.x];
}

// 3. fill packed adjacency entries (src, w_premult). Pad slots stay (0, 0.0f)
//    from the memset and contribute exactly zero in the gathers.
__global__ void fill_kernel(const int* __restrict__ eu, const int* __restrict__ ei,
                            int E, int nu) {
    int e = blockIdx.x * blockDim.x + threadIdx.x;
    if (e >= E) return;
    int u = eu[e];
    int r2 = nu + ei[e];
    float w = g_rs[u] * g_rs[r2];
    int wb = __float_as_int(w);
    int2* adj = reinterpret_cast<int2*>(g_adj4);
    int p1 = atomicAdd(&g_cur[u], 1);
    adj[(size_t)g_off[u] + p1] = make_int2(r2, wb);
    int p2 = atomicAdd(&g_cur[r2], 1);
    adj[(size_t)g_off[r2] + p2] = make_int2(u, wb);
}

// 4a. fp16 copy of stacked tables
__global__ void convert_kernel(const float2* __restrict__ ut, const float2* __restrict__ it,
                               int nu2, int ntot2) {
    int i = blockIdx.x * blockDim.x + threadIdx.x;
    if (i < ntot2) {
        float2 v = (i < nu2) ? ut[i] : it[i - nu2];
        g_t16[i] = __floats2half2_rn(v.x, v.y);
    }
}

// gather with premultiplied weights: aligned int4 pair loop, no tail scalars.
__device__ __forceinline__ float2 gather_row_p(const __half2* __restrict__ src,
                                               int node, int lane) {
    int beg = g_off[node];
    int end = g_off[node + 1];
    const int4* a4 = reinterpret_cast<const int4*>(
        reinterpret_cast<const int2*>(g_adj4) + beg);
    int npair = (end - beg) >> 1;
    float sx = 0.0f, sy = 0.0f;
    int j = 0;
    for (; j + 1 < npair; j += 2) {
        int4 p0 = __ldg(&a4[j]);
        int4 p1 = __ldg(&a4[j + 1]);
        float2 v0 = __half22float2(__ldg(src + ((size_t)p0.x << 5) + lane));
        float2 v1 = __half22float2(__ldg(src + ((size_t)p0.z << 5) + lane));
        float2 v2 = __half22float2(__ldg(src + ((size_t)p1.x << 5) + lane));
        float2 v3 = __half22float2(__ldg(src + ((size_t)p1.z << 5) + lane));
        float w0 = __int_as_float(p0.y), w1 = __int_as_float(p0.w);
        float w2 = __int_as_float(p1.y), w3 = __int_as_float(p1.w);
        sx += w0 * v0.x + w1 * v1.x + w2 * v2.x + w3 * v3.x;
        sy += w0 * v0.y + w1 * v1.y + w2 * v2.y + w3 * v3.y;
    }
    if (j < npair) {
        int4 p0 = __ldg(&a4[j]);
        float2 v0 = __half22float2(__ldg(src + ((size_t)p0.x << 5) + lane));
        float2 v1 = __half22float2(__ldg(src + ((size_t)p0.z << 5) + lane));
        float w0 = __int_as_float(p0.y), w1 = __int_as_float(p0.w);
        sx += w0 * v0.x + w1 * v1.x;
        sy += w0 * v0.y + w1 * v1.y;
    }
    return make_float2(sx, sy);
}

// 4b. full-graph propagation layer: dst = gather(src), fp16 out
__global__ void gatherH_kernel(const __half2* __restrict__ src,
                               __half2* __restrict__ dst, int N) {
    int warp = (blockIdx.x * blockDim.x + threadIdx.x) >> 5;
    int lane = threadIdx.x & 31;
    if (warp >= N) return;
    float2 s = gather_row_p(src, warp, lane);
    dst[(size_t)warp * (EMB_D / 2) + lane] = __floats2half2_rn(s.x, s.y);
}

// 5. fused final layer + scoring: one warp per batch element.
__global__ void score_kernel(const float* __restrict__ ut, const float* __restrict__ it,
                             const int* __restrict__ users, const int* __restrict__ pos,
                             const int* __restrict__ neg,
                             const __half2* __restrict__ x1h,
                             const __half2* __restrict__ x2h,
                             float* __restrict__ out, int B, int nu) {
    int warp = (blockIdx.x * blockDim.x + threadIdx.x) >> 5;
    int lane = threadIdx.x & 31;
    if (warp >= B) return;

    int nodes[3];
    nodes[0] = users[warp];
    nodes[1] = nu + pos[warp];
    nodes[2] = nu + neg[warp];

    float2 f[3];
    float rg = 0.0f;
    #pragma unroll
    for (int k = 0; k < 3; ++k) {
        int node = nodes[k];
        float2 x3 = gather_row_p(x2h, node, lane);
        const float* base0 = (node < nu) ? (ut + (size_t)node * EMB_D)
                                         : (it + (size_t)(node - nu) * EMB_D);
        float2 x0 = reinterpret_cast<const float2*>(base0)[lane];
        float2 x1 = __half22float2(x1h[(size_t)node * (EMB_D / 2) + lane]);
        float2 x2 = __half22float2(x2h[(size_t)node * (EMB_D / 2) + lane]);
        f[k] = make_float2(0.25f * (x0.x + x1.x + x2.x + x3.x),
                           0.25f * (x0.y + x1.y + x2.y + x3.y));
        rg += x0.x * x0.x + x0.y * x0.y;
    }

    float ps = f[0].x * f[1].x + f[0].y * f[1].y;
    float ns = f[0].x * f[2].x + f[0].y * f[2].y;

    #pragma unroll
    for (int o = 16; o > 0; o >>= 1) {
        ps += __shfl_down_sync(0xFFFFFFFFu, ps, o);
        ns += __shfl_down_sync(0xFFFFFFFFu, ns, o);
        rg += __shfl_down_sync(0xFFFFFFFFu, rg, o);
    }
    if (lane == 0) {
        out[warp]     = ps;
        out[B + warp] = ns;
        atomicAdd(&out[2 * B], rg * (1e-4f / (float)B));
    }
}

// ---------------------------------------------------------------------------
extern "C" void kernel_launch(void* const* d_in, const int* in_sizes, int n_in,
                              void* d_out, int out_size) {
    const float* ut    = (const float*)d_in[0];
    const float* it    = (const float*)d_in[1];
    const int*   eu    = (const int*)d_in[2];
    const int*   ei    = (const int*)d_in[3];
    const int*   users = (const int*)d_in[4];
    const int*   pos   = (const int*)d_in[5];
    const int*   neg   = (const int*)d_in[6];
    float*       out   = (float*)d_out;

    const int n_users = in_sizes[0] / EMB_D;
    const int n_items = in_sizes[1] / EMB_D;
    const int E       = in_sizes[2];
    const int B       = in_sizes[4];
    const int N       = n_users + n_items;

    void *p_deg, *p_cur, *p_adj, *p_t16, *p_x1h, *p_x2h;
    cudaGetSymbolAddress(&p_deg, g_deg);
    cudaGetSymbolAddress(&p_cur, g_cur);
    cudaGetSymbolAddress(&p_adj, g_adj4);
    cudaGetSymbolAddress(&p_t16, g_t16);
    cudaGetSymbolAddress(&p_x1h, g_x1h);
    cudaGetSymbolAddress(&p_x2h, g_x2h);

    const int T = 256;

    // adjacency memset (pads must read as (0, 0.0f))
    cudaMemsetAsync(p_adj, 0, ((size_t)2 * E + N + 8) * 8, 0);

    // fp16 table copy (independent of CSR chain)
    const int ntot2 = N * (EMB_D / 2);
    convert_kernel<<<(ntot2 + T - 1) / T, T>>>((const float2*)ut, (const float2*)it,
                                               n_users * (EMB_D / 2), ntot2);

    // 1: degrees
    cudaMemsetAsync(p_deg, 0, (size_t)N * sizeof(int), 0);
    deg_kernel<<<(E + T - 1) / T, T>>>(eu, ei, E, n_users);

    // 2: rs + exclusive scan of padded degrees -> g_off (off even everywhere)
    const int n_scan = N + 1;
    const int nb = (n_scan + SCAN_B - 1) / SCAN_B;
    scan1_kernel<<<nb, SCAN_B>>>(n_scan, N);
    scan2_kernel<<<1, SCAN_B>>>(nb);
    scan3_kernel<<<nb, SCAN_B>>>(n_scan);

    // 3: adjacency fill
    cudaMemsetAsync(p_cur, 0, (size_t)N * sizeof(int), 0);
    fill_kernel<<<(E + T - 1) / T, T>>>(eu, ei, E, n_users);

    // 4: two full propagation layers (fp16 storage)
    const int wpb = T / 32;
    const int gblocks = (N + wpb - 1) / wpb;
    gatherH_kernel<<<gblocks, T>>>((const __half2*)p_t16, (__half2*)p_x1h, N);
    gatherH_kernel<<<gblocks, T>>>((const __half2*)p_x1h, (__half2*)p_x2h, N);

    // 5: fused final layer + scoring
    cudaMemsetAsync(out + 2 * B, 0, sizeof(float), 0);
    score_kernel<<<(B + wpb - 1) / wpb, T>>>(ut, it, users, pos, neg,
                                             (const __half2*)p_x1h,
                                             (const __half2*)p_x2h,
                                             out, B, n_users);
}